// round 6
// baseline (speedup 1.0000x reference)
#include <cuda_runtime.h>
#include <cuda_bf16.h>

#define NPTS 1024
#define KPOS 512
#define KSEL 32
#define FULLMASK 0xFFFFFFFFu

typedef unsigned long long ull;

// ---- packed f32x2 helpers (lanewise IEEE rn — bit-identical to scalar rn ops)
__device__ __forceinline__ ull pk2(float a, float b) {
    ull r; asm("mov.b64 %0, {%1, %2};" : "=l"(r) : "f"(a), "f"(b)); return r;
}
__device__ __forceinline__ void upk2(ull v, float& a, float& b) {
    asm("mov.b64 {%0, %1}, %2;" : "=f"(a), "=f"(b) : "l"(v));
}
__device__ __forceinline__ ull addx2(ull a, ull b) {
    ull r; asm("add.rn.f32x2 %0, %1, %2;" : "=l"(r) : "l"(a), "l"(b)); return r;
}
__device__ __forceinline__ ull mulx2(ull a, ull b) {
    ull r; asm("mul.rn.f32x2 %0, %1, %2;" : "=l"(r) : "l"(a), "l"(b)); return r;
}

// ============================================================================
// Fused kernel: one CTA (512 threads) per submap.
//  Phase 1 (16 warps): radix-select 512 xy-closest of 1024 (exact jax top_k
//    tie semantics), compact into smem qpos (slot order = index order), seed.
//  Phase 2 (warps 0-1, others exit): 31-step FPS, 8 pts/lane in registers,
//    cross-warp argmax via named barrier + double-buffered smem slots.
//  Phase 3 (warp 0): per-lane MLP (32->16->8->1, relu/relu/softplus) + output.
// ============================================================================
__global__ __launch_bounds__(512, 2)
void detector_fused(const float* __restrict__ pos,
                    const float* __restrict__ x,
                    const float* __restrict__ W1, const float* __restrict__ b1,
                    const float* __restrict__ W2, const float* __restrict__ b2,
                    const float* __restrict__ W3, const float* __restrict__ b3,
                    float* __restrict__ out_w, float* __restrict__ out_i)
{
    __shared__ unsigned int hist[2048];
    __shared__ unsigned int sstate[2];     // [0]=prefix/T  [1]=kth/r
    __shared__ unsigned int wA[16], wB[16];
    __shared__ ull wpk[16];
    __shared__ ull spk;
    __shared__ int sseed;
    __shared__ float4 qpos[KPOS];
    __shared__ ull xw[2][2];               // [buf][warp] FPS cross-warp exchange
    __shared__ float sW1[512]; __shared__ float sb1[16];
    __shared__ float sW2[128]; __shared__ float sb2[8];
    __shared__ float sW3[8];   __shared__ float sb3v;

    const int t = threadIdx.x;
    const int w = t >> 5, lane = t & 31;
    const int b = blockIdx.x;
    const long base = (long)b * NPTS;

    // ---- stage MLP params (512 threads) ----
    sW1[t] = W1[t];
    if (t < 128) sW2[t] = W2[t];
    if (t < 16)  sb1[t] = b1[t];
    if (t < 8)   sb2[t] = b2[t];
    if (t < 8)   sW3[t] = W3[t];
    if (t == 0)  { sb3v = b3[0]; sstate[0] = 0u; sstate[1] = KPOS; }

    // ---- load 2 points per thread (indices 2t, 2t+1) ----
    const float2* p2 = (const float2*)(pos + 3 * base + 6 * t);
    const float2 v0 = p2[0], v1 = p2[1], v2 = p2[2];
    const float pxa = v0.x, pya = v0.y, pza = v1.x;
    const float pxb = v1.y, pyb = v2.x, pzb = v2.y;
    const int ia = 2 * t, ib = 2 * t + 1;

    const unsigned int kba =
        __float_as_uint(__fsqrt_rn(__fadd_rn(__fmul_rn(pxa,pxa), __fmul_rn(pya,pya))));
    const unsigned int kbb =
        __float_as_uint(__fsqrt_rn(__fadd_rn(__fmul_rn(pxb,pxb), __fmul_rn(pyb,pyb))));

    // ---- radix select KPOS-th smallest: 3 passes (11/11/10 bits) ----
    {
        const int shifts[3] = {21, 10, 0};
        const int bitsv [3] = {11, 11, 10};
        #pragma unroll 1
        for (int p = 0; p < 3; p++) {
            const int shift = shifts[p];
            hist[t] = 0u; hist[t + 512] = 0u; hist[t + 1024] = 0u; hist[t + 1536] = 0u;
            __syncthreads();
            const unsigned int prefix = sstate[0], kth = sstate[1];
            const int sb = shift + bitsv[p];
            const unsigned int hm = (sb >= 32) ? 0u : (0xFFFFFFFFu << sb);
            const unsigned int dm = (1u << bitsv[p]) - 1u;
            if ((kba & hm) == prefix) atomicAdd(&hist[(kba >> shift) & dm], 1u);
            if ((kbb & hm) == prefix) atomicAdd(&hist[(kbb >> shift) & dm], 1u);
            __syncthreads();

            // block prefix over 2048 bins; thread owns bins {4t..4t+3}
            const unsigned int h0 = hist[4*t], h1 = hist[4*t+1],
                               h2 = hist[4*t+2], h3 = hist[4*t+3];
            const unsigned int s = h0 + h1 + h2 + h3;
            unsigned int inc = s;
            #pragma unroll
            for (int d = 1; d < 32; d <<= 1) {
                unsigned int v = __shfl_up_sync(FULLMASK, inc, d);
                if (lane >= d) inc += v;
            }
            if (lane == 31) wA[w] = inc;
            __syncthreads();
            if (t < 32) {
                unsigned int wv = (t < 16) ? wA[t] : 0u;
                unsigned int winc = wv;
                #pragma unroll
                for (int d = 1; d < 32; d <<= 1) {
                    unsigned int v = __shfl_up_sync(FULLMASK, winc, d);
                    if (t >= d) winc += v;
                }
                if (t < 16) wA[t] = winc - wv;
            }
            __syncthreads();
            unsigned int c = wA[w] + (inc - s);   // exclusive prefix of bin 4t
            const unsigned int hv[4] = {h0, h1, h2, h3};
            #pragma unroll
            for (int i = 0; i < 4; i++) {
                if (kth > c && kth <= c + hv[i]) {
                    sstate[0] = prefix | ((unsigned int)(4 * t + i) << shift);
                    sstate[1] = kth - c;
                }
                c += hv[i];
            }
            __syncthreads();
        }
    }
    const unsigned int T = sstate[0];
    const unsigned int r = sstate[1];

    // ---- closed-form tie handling + compaction + seed ----
    const bool ltA = (kba < T), tdA = (kba == T);
    const bool ltB = (kbb < T), tdB = (kbb == T);
    const unsigned int balLa = __ballot_sync(FULLMASK, ltA);
    const unsigned int balLb = __ballot_sync(FULLMASK, ltB);
    const unsigned int balTa = __ballot_sync(FULLMASK, tdA);
    const unsigned int balTb = __ballot_sync(FULLMASK, tdB);
    if (lane == 0) {
        wA[w] = __popc(balLa) + __popc(balLb);
        wB[w] = __popc(balTa) + __popc(balTb);
    }
    // seed: block argmin of (key, index); min over own two points first
    ull pk = (((ull)kba) << 32) | (unsigned int)ia;
    {
        const ull pkb2 = (((ull)kbb) << 32) | (unsigned int)ib;
        if (pkb2 < pk) pk = pkb2;
        #pragma unroll
        for (int off = 16; off > 0; off >>= 1) {
            ull o2 = __shfl_xor_sync(FULLMASK, pk, off);
            if (o2 < pk) pk = o2;
        }
        if (lane == 0) wpk[w] = pk;
    }
    __syncthreads();
    if (t < 32) {
        unsigned int a0 = (t < 16) ? wA[t] : 0u;
        unsigned int b0 = (t < 16) ? wB[t] : 0u;
        unsigned int iaa = a0, ibb = b0;
        #pragma unroll
        for (int d = 1; d < 32; d <<= 1) {
            unsigned int va = __shfl_up_sync(FULLMASK, iaa, d);
            unsigned int vb = __shfl_up_sync(FULLMASK, ibb, d);
            if (t >= d) { iaa += va; ibb += vb; }
        }
        if (t < 16) { wA[t] = iaa - a0; wB[t] = ibb - b0; }

        ull v2m = (t < 16) ? wpk[t] : ~0ull;
        #pragma unroll
        for (int off = 16; off > 0; off >>= 1) {
            ull o2 = __shfl_xor_sync(FULLMASK, v2m, off);
            if (o2 < v2m) v2m = o2;
        }
        if (t == 0) spk = v2m;
    }
    __syncthreads();
    {
        const unsigned int lm = (1u << lane) - 1u;
        const unsigned int seedIdx = (unsigned int)(spk & 0xFFFFFFFFull);
        // counts of earlier-index points (warp-interleaved pairs: a then b per lane)
        unsigned int clt = wA[w] + __popc(balLa & lm) + __popc(balLb & lm);
        unsigned int ctd = wB[w] + __popc(balTa & lm) + __popc(balTb & lm);
        // point a
        if (ltA || (tdA && ctd < r)) {
            const int slot = (int)(clt + (ctd < r ? ctd : r));
            qpos[slot] = make_float4(pxa, pya, pza, __int_as_float(ia));
            if ((unsigned int)ia == seedIdx) sseed = slot;
        }
        clt += ltA ? 1u : 0u;
        ctd += tdA ? 1u : 0u;
        // point b
        if (ltB || (tdB && ctd < r)) {
            const int slot = (int)(clt + (ctd < r ? ctd : r));
            qpos[slot] = make_float4(pxb, pyb, pzb, __int_as_float(ib));
            if ((unsigned int)ib == seedIdx) sseed = slot;
        }
    }
    __syncthreads();

    // ---- Phase 2: FPS on warps 0-1; all other warps retire ----
    if (w >= 2) return;

    const int ww = w;                     // warp-in-pair
    const int pbase = ww * 32 + lane;     // slot stride base

    ull pxp[4], pyp[4], pzp[4];
    float md[8];
    #pragma unroll
    for (int k = 0; k < 4; k++) {
        const float4 a0 = qpos[(2*k)     * 64 + pbase];
        const float4 a1 = qpos[(2*k + 1) * 64 + pbase];
        pxp[k] = pk2(a0.x, a1.x);
        pyp[k] = pk2(a0.y, a1.y);
        pzp[k] = pk2(a0.z, a1.z);
    }

    const int s0 = sseed;
    float4 q = qpos[s0];
    int mysel = s0;   // warp0 lane 'step' records the step'th selection

    {
        const ull qnx = pk2(-q.x, -q.x), qny = pk2(-q.y, -q.y), qnz = pk2(-q.z, -q.z);
        #pragma unroll
        for (int k = 0; k < 4; k++) {
            const ull dx = addx2(pxp[k], qnx);
            const ull dy = addx2(pyp[k], qny);
            const ull dz = addx2(pzp[k], qnz);
            const ull d2 = addx2(addx2(mulx2(dx,dx), mulx2(dy,dy)), mulx2(dz,dz));
            upk2(d2, md[2*k], md[2*k+1]);
        }
    }

    #pragma unroll 1
    for (int step = 1; step < KSEL; step++) {
        float best = md[0]; int bs = pbase;
        #pragma unroll
        for (int j = 1; j < 8; j++) {
            const int s = j * 64 + pbase;
            if (md[j] > best) { best = md[j]; bs = s; }
        }
        const unsigned int bb = __float_as_uint(best);
        const unsigned int wm = __reduce_max_sync(FULLMASK, bb);
        const unsigned int cand = (bb == wm) ? (unsigned int)bs : 0xFFFFFFFFu;
        const unsigned int ws = __reduce_min_sync(FULLMASK, cand);
        const int buf = step & 1;
        if (lane == 0)
            xw[buf][ww] = (((ull)wm) << 32) | (unsigned int)(~ws);
        asm volatile("bar.sync 1, 64;" ::: "memory");
        const ull p0 = xw[buf][0];
        const ull p1 = xw[buf][1];
        const ull win = (p0 > p1) ? p0 : p1;   // max dist, tie -> min slot
        const int cur = (int)(~(unsigned int)(win & 0xFFFFFFFFull));
        if (ww == 0 && lane == step) mysel = cur;
        q = qpos[cur];
        const ull qnx = pk2(-q.x, -q.x), qny = pk2(-q.y, -q.y), qnz = pk2(-q.z, -q.z);
        #pragma unroll
        for (int k = 0; k < 4; k++) {
            const ull dx = addx2(pxp[k], qnx);
            const ull dy = addx2(pyp[k], qny);
            const ull dz = addx2(pzp[k], qnz);
            const ull d2 = addx2(addx2(mulx2(dx,dx), mulx2(dy,dy)), mulx2(dz,dz));
            float a2, c2;
            upk2(d2, a2, c2);
            md[2*k]   = fminf(md[2*k],   a2);
            md[2*k+1] = fminf(md[2*k+1], c2);
        }
    }

    if (ww != 0) return;

    // ---- Phase 3: per-lane MLP (warp 0; lane = selection step) ----
    const float4 qs = qpos[mysel];
    const int o = __float_as_int(qs.w);
    const float* xr = x + (base + o) * 32;

    float h1[16];
    #pragma unroll
    for (int k2 = 0; k2 < 16; k2++) h1[k2] = sb1[k2];
    #pragma unroll
    for (int i = 0; i < 32; i += 4) {
        const float4 xv = *(const float4*)(xr + i);
        #pragma unroll
        for (int k2 = 0; k2 < 16; k2++) {
            h1[k2] = fmaf(xv.x, sW1[(i+0) * 16 + k2], h1[k2]);
            h1[k2] = fmaf(xv.y, sW1[(i+1) * 16 + k2], h1[k2]);
            h1[k2] = fmaf(xv.z, sW1[(i+2) * 16 + k2], h1[k2]);
            h1[k2] = fmaf(xv.w, sW1[(i+3) * 16 + k2], h1[k2]);
        }
    }
    #pragma unroll
    for (int k2 = 0; k2 < 16; k2++) h1[k2] = fmaxf(h1[k2], 0.f);

    float h2[8];
    #pragma unroll
    for (int k2 = 0; k2 < 8; k2++) h2[k2] = sb2[k2];
    #pragma unroll
    for (int j = 0; j < 16; j++) {
        const float hj = h1[j];
        #pragma unroll
        for (int k2 = 0; k2 < 8; k2++)
            h2[k2] = fmaf(hj, sW2[j * 8 + k2], h2[k2]);
    }
    float acc = sb3v;
    #pragma unroll
    for (int j = 0; j < 8; j++)
        acc = fmaf(fmaxf(h2[j], 0.f), sW3[j], acc);

    const float s = fmaxf(acc, 0.f) + log1pf(expf(-fabsf(acc)));

    out_w[b * KSEL + lane] = s;
    out_i[b * KSEL + lane] = (float)o;
}

extern "C" void kernel_launch(void* const* d_in, const int* in_sizes, int n_in,
                              void* d_out, int out_size)
{
    const float* x   = (const float*)d_in[0];
    const float* pos = (const float*)d_in[1];
    // d_in[2] = batch (unused; regular layout)
    const float* W1 = (const float*)d_in[3];
    const float* b1 = (const float*)d_in[4];
    const float* W2 = (const float*)d_in[5];
    const float* b2 = (const float*)d_in[6];
    const float* W3 = (const float*)d_in[7];
    const float* b3 = (const float*)d_in[8];

    const int B = in_sizes[2] / NPTS;   // 2048
    float* out_w = (float*)d_out;
    float* out_i = out_w + (size_t)B * KSEL;

    detector_fused<<<B, 512>>>(pos, x, W1, b1, W2, b2, W3, b3, out_w, out_i);
}